// round 10
// baseline (speedup 1.0000x reference)
#include <cuda_runtime.h>
#include <cstdint>

#define TND 65536   // T * N_
#define NDIM 256    // DIMS
#define NKEY 64     // M

// Output section offsets (flattened tuple, fp32)
#define OFF_UPMEM 33554432ull   // 512*65536
#define OFF_SQ    33570816ull
#define OFF_SM    37765120ull
#define OFF_SPR   41959424ull
#define OFF_GTH   42024960ull

// Scratch (device globals: allocation-free)
__device__ float    g_score[(size_t)TND * NKEY];   // 16 MB
__device__ __align__(16) float g_qupd[NKEY * NDIM];
__device__ float    g_bmax[256 * NKEY];            // per-score-block col max
__device__ float    g_bsum[256 * NKEY];            // per-score-block col expsum
__device__ float    g_cmaxf[NKEY];
__device__ float    g_csum[NKEY];

typedef unsigned long long ull;

__device__ __forceinline__ ull pack2(float lo, float hi) {
    ull r; asm("mov.b64 %0, {%1,%2};" : "=l"(r) : "f"(lo), "f"(hi)); return r;
}
__device__ __forceinline__ void unpack2(ull v, float& lo, float& hi) {
    asm("mov.b64 {%0,%1}, %2;" : "=f"(lo), "=f"(hi) : "l"(v));
}
__device__ __forceinline__ ull fma2(ull a, ull b, ull c) {
    ull d; asm("fma.rn.f32x2 %0, %1, %2, %3;" : "=l"(d) : "l"(a), "l"(b), "l"(c)); return d;
}

// K1: score[i][m] = sum_d query[d][i]*keys[m][d]; fused per-block col-max AND
// per-block col exp-sum (local-max form) — scores never re-read for colsum.
__global__ __launch_bounds__(256, 2) void k_score(const float* __restrict__ query,
                                                  const float* __restrict__ keys) {
    extern __shared__ float sm1[];        // keysT[256][64]; reused afterwards
    float* keysT = sm1;
    int tid = threadIdx.x;
    for (int idx = tid; idx < NKEY * NDIM; idx += 256) {
        int m = idx >> 8, d = idx & 255;
        keysT[d * NKEY + m] = keys[idx];
    }
    __syncthreads();

    int i = blockIdx.x * 256 + tid;
    ull acc[32];
#pragma unroll
    for (int j = 0; j < 32; j++) acc[j] = 0ull;

#pragma unroll 4
    for (int d = 0; d < NDIM; d++) {
        float q = __ldg(query + (size_t)d * TND + i);
        ull qq = pack2(q, q);
        const ulonglong2* kt = (const ulonglong2*)(keysT + d * NKEY);
#pragma unroll
        for (int j = 0; j < 16; j++) {
            ulonglong2 kk = kt[j];
            acc[2 * j]     = fma2(qq, kk.x, acc[2 * j]);
            acc[2 * j + 1] = fma2(qq, kk.y, acc[2 * j + 1]);
        }
    }

    ull* srow = (ull*)(g_score + (size_t)i * NKEY);
#pragma unroll
    for (int j = 0; j < 32; j++) srow[j] = acc[j];

    __syncthreads();   // done with keysT; reuse smem
    float* wmax  = sm1;        // [8][64]
    float* bmaxs = sm1 + 512;  // [64]
    float* wsum  = sm1 + 576;  // [8][64]
    int w = tid >> 5, lane = tid & 31;
#pragma unroll
    for (int j = 0; j < 32; j++) {
        float a, b; unpack2(acc[j], a, b);
#pragma unroll
        for (int o = 16; o; o >>= 1) {
            a = fmaxf(a, __shfl_xor_sync(0xffffffffu, a, o));
            b = fmaxf(b, __shfl_xor_sync(0xffffffffu, b, o));
        }
        if (lane == 0) { wmax[w * NKEY + 2 * j] = a; wmax[w * NKEY + 2 * j + 1] = b; }
    }
    __syncthreads();
    if (tid < NKEY) {
        float mx = wmax[tid];
#pragma unroll
        for (int ww = 1; ww < 8; ww++) mx = fmaxf(mx, wmax[ww * NKEY + tid]);
        bmaxs[tid] = mx;
        g_bmax[blockIdx.x * NKEY + tid] = mx;
    }
    __syncthreads();
    // block-local exp sums per column (scores still in registers)
#pragma unroll
    for (int j = 0; j < 32; j++) {
        float a, b; unpack2(acc[j], a, b);
        float e0 = __expf(a - bmaxs[2 * j]);
        float e1 = __expf(b - bmaxs[2 * j + 1]);
#pragma unroll
        for (int o = 16; o; o >>= 1) {
            e0 += __shfl_xor_sync(~0u, e0, o);
            e1 += __shfl_xor_sync(~0u, e1, o);
        }
        if (lane == 0) { wsum[w * NKEY + 2 * j] = e0; wsum[w * NKEY + 2 * j + 1] = e1; }
    }
    __syncthreads();
    if (tid < NKEY) {
        float s = 0.f;
#pragma unroll
        for (int ww = 0; ww < 8; ww++) s += wsum[ww * NKEY + tid];
        g_bsum[blockIdx.x * NKEY + tid] = s;
    }
}

// K2: per-column global max + rescaled sum from 256 block partials; also zero g_qupd.
__global__ void k_fix() {
    __shared__ float s1[8], s2[8], sG;
    int m = blockIdx.x, t = threadIdx.x;
    g_qupd[m * NDIM + t] = 0.f;
    float L = g_bmax[t * NKEY + m];
    float mx = L;
#pragma unroll
    for (int o = 16; o; o >>= 1) mx = fmaxf(mx, __shfl_xor_sync(~0u, mx, o));
    if ((t & 31) == 0) s1[t >> 5] = mx;
    __syncthreads();
    if (t == 0) {
        float G = s1[0];
#pragma unroll
        for (int ww = 1; ww < 8; ww++) G = fmaxf(G, s1[ww]);
        sG = G;
    }
    __syncthreads();
    float G = sG;
    float S = g_bsum[t * NKEY + m] * __expf(L - G);
#pragma unroll
    for (int o = 16; o; o >>= 1) S += __shfl_xor_sync(~0u, S, o);
    if ((t & 31) == 0) s2[t >> 5] = S;
    __syncthreads();
    if (t == 0) {
        float s = 0.f;
#pragma unroll
        for (int ww = 0; ww < 8; ww++) s += s2[ww];
        g_csum[m] = s;
        g_cmaxf[m] = G;
    }
}

// K3: per-row: top2, both softmax outputs, gathering, triplet, qout copy,
// query_update RED. (concat GEMV moved to k_concat.)
__global__ __launch_bounds__(256, 2) void k_main(const float* __restrict__ query,
                                                 const float* __restrict__ keys,
                                                 float* __restrict__ out) {
    extern __shared__ float sm3[];
    float* skeysT = sm3;            // [256][64]
    float* scmax  = sm3 + 16384;    // [64]
    float* scsinv = sm3 + 16448;    // [64]
    int tid = threadIdx.x;
    for (int idx = tid; idx < NKEY * NDIM; idx += 256) {
        int m = idx >> 8, d = idx & 255;
        skeysT[d * NKEY + m] = keys[idx];
    }
    if (tid < NKEY) { scmax[tid] = g_cmaxf[tid]; scsinv[tid] = 1.f / g_csum[tid]; }
    __syncthreads();

    int i = blockIdx.x * 256 + tid;
    const float4* s4 = (const float4*)(g_score + (size_t)i * NKEY);

    // pass 1: rowmax + top2 indices
    float v1 = -3.4e38f, v2 = -3.4e38f; int g1 = 0, g2 = 0;
#pragma unroll
    for (int j = 0; j < 16; j++) {
        float4 f = s4[j];
        float vv[4] = {f.x, f.y, f.z, f.w};
#pragma unroll
        for (int k = 0; k < 4; k++) {
            float s = vv[k]; int m = 4 * j + k;
            if (s > v1) { v2 = v1; g2 = g1; v1 = s; g1 = m; }
            else if (s > v2) { v2 = s; g2 = m; }
        }
    }
    float rowmax = v1;

    // pass 2a: score_query writes + rowsum
    float rowsum = 0.f;
    float4* sqout = (float4*)(out + OFF_SQ + (size_t)i * NKEY);
#pragma unroll
    for (int j = 0; j < 16; j++) {
        float4 f = s4[j];
        rowsum += (__expf(f.x - rowmax) + __expf(f.y - rowmax))
                + (__expf(f.z - rowmax) + __expf(f.w - rowmax));
        float4 sq;
        sq.x = __expf(f.x - scmax[4 * j])     * scsinv[4 * j];
        sq.y = __expf(f.y - scmax[4 * j + 1]) * scsinv[4 * j + 1];
        sq.z = __expf(f.z - scmax[4 * j + 2]) * scsinv[4 * j + 2];
        sq.w = __expf(f.w - scmax[4 * j + 3]) * scsinv[4 * j + 3];
        sqout[j] = sq;
    }
    // pass 2b: score_memory writes (recompute exps; score row is L1-hot)
    float inv = 1.f / rowsum;
    float4* smout = (float4*)(out + OFF_SM + (size_t)i * NKEY);
#pragma unroll
    for (int j = 0; j < 16; j++) {
        float4 f = s4[j];
        float4 o;
        o.x = __expf(f.x - rowmax) * inv; o.y = __expf(f.y - rowmax) * inv;
        o.z = __expf(f.z - rowmax) * inv; o.w = __expf(f.w - rowmax) * inv;
        smout[j] = o;
    }

    // scatter weight: score[i][g1] == rowmax
    float w = __expf(rowmax - scmax[g1]);

    float dpos2 = 0.f, dneg2 = 0.f;
    float* gout = out + OFF_GTH + (size_t)i * NDIM;
    float* qout = out + i;                        // updated_query first half
    float* qup  = g_qupd + g1 * NDIM;

    for (int c = 0; c < 32; c++) {
        int d0 = c * 8;
        float q[8];
#pragma unroll
        for (int k = 0; k < 8; k++) q[k] = __ldg(query + (size_t)(d0 + k) * TND + i);
#pragma unroll
        for (int k = 0; k < 8; k++) qout[(size_t)(d0 + k) * TND] = q[k];

        float gbuf[8], wq[8];
#pragma unroll
        for (int k = 0; k < 8; k++) {
            int d = d0 + k;
            float kp = skeysT[d * NKEY + g1];
            float kn = skeysT[d * NKEY + g2];
            float dq = q[k] - kp;
            gbuf[k] = dq * dq;
            float tp = dq + 1e-6f;          dpos2 = fmaf(tp, tp, dpos2);
            float tn = (q[k] - kn) + 1e-6f; dneg2 = fmaf(tn, tn, dneg2);
            wq[k] = w * q[k];
        }
        *(float4*)(gout + d0)     = make_float4(gbuf[0], gbuf[1], gbuf[2], gbuf[3]);
        *(float4*)(gout + d0 + 4) = make_float4(gbuf[4], gbuf[5], gbuf[6], gbuf[7]);
        atomicAdd((float4*)(qup + d0),     make_float4(wq[0], wq[1], wq[2], wq[3]));
        atomicAdd((float4*)(qup + d0 + 4), make_float4(wq[4], wq[5], wq[6], wq[7]));
    }

    out[OFF_SPR + i] = fmaxf(sqrtf(dpos2) - sqrtf(dneg2) + 1.f, 0.f);
}

// K4: concat = score_memory @ keys, written transposed: out[(256+d)*TND + i].
// CTA tile 64 rows x 256 cols; thread tile 4 rows x 16 cols, packed fma2.
__global__ __launch_bounds__(256, 2) void k_concat(const float* __restrict__ keys,
                                                   float* __restrict__ out) {
    extern __shared__ float smc[];
    float* skc = smc;            // keys [64][256]
    float* smt = smc + 16384;    // sm tile [64][65]
    int tid = threadIdx.x;

    const float4* kg = (const float4*)keys;
    float4* ks4 = (float4*)skc;
    for (int idx = tid; idx < NKEY * NDIM / 4; idx += 256) ks4[idx] = kg[idx];

    const float4* smg = (const float4*)(out + OFF_SM + (size_t)blockIdx.x * 64 * NKEY);
    for (int idx = tid; idx < 64 * NKEY / 4; idx += 256) {
        float4 v = smg[idx];
        int row = idx >> 4;          // 16 float4 per 64-col row
        int k4 = (idx & 15) * 4;
        float* dst = smt + row * 65 + k4;
        dst[0] = v.x; dst[1] = v.y; dst[2] = v.z; dst[3] = v.w;
    }
    __syncthreads();

    int ty = tid & 15, tx = tid >> 4;
    int r0 = ty * 4, c0 = tx * 16;
    ull acc[4][8];
#pragma unroll
    for (int r = 0; r < 4; r++)
#pragma unroll
        for (int j = 0; j < 8; j++) acc[r][j] = 0ull;

    const float* ap = smt + r0 * 65;
#pragma unroll 4
    for (int k = 0; k < NKEY; k++) {
        float a0 = ap[k], a1 = ap[65 + k], a2 = ap[130 + k], a3 = ap[195 + k];
        ull q0 = pack2(a0, a0), q1 = pack2(a1, a1), q2 = pack2(a2, a2), q3 = pack2(a3, a3);
        const ulonglong2* bp = (const ulonglong2*)(skc + k * NDIM + c0);
        ulonglong2 ba = bp[0], bb = bp[1], bc = bp[2], bd = bp[3];
        ull B[8] = {ba.x, ba.y, bb.x, bb.y, bc.x, bc.y, bd.x, bd.y};
#pragma unroll
        for (int j = 0; j < 8; j++) {
            acc[0][j] = fma2(q0, B[j], acc[0][j]);
            acc[1][j] = fma2(q1, B[j], acc[1][j]);
            acc[2][j] = fma2(q2, B[j], acc[2][j]);
            acc[3][j] = fma2(q3, B[j], acc[3][j]);
        }
    }

    // unpack and store: for col c, float4 over 4 consecutive rows (coalesced)
    float accf[4][16];
#pragma unroll
    for (int r = 0; r < 4; r++)
#pragma unroll
        for (int j = 0; j < 8; j++) unpack2(acc[r][j], accf[r][2 * j], accf[r][2 * j + 1]);

    size_t ibase = (size_t)blockIdx.x * 64 + r0;
    float* obase = out + (size_t)NDIM * TND + ibase;
#pragma unroll
    for (int j = 0; j < 16; j++) {
        int c = c0 + j;
        float4 v = make_float4(accf[0][j], accf[1][j], accf[2][j], accf[3][j]);
        *(float4*)(obase + (size_t)c * TND) = v;
    }
}

// K5: updated_memory = l2_normalize(query_update + keys)
__global__ void k_mem(const float* __restrict__ keys, float* __restrict__ out) {
    int m = blockIdx.x, d = threadIdx.x;
    float v = g_qupd[m * NDIM + d] + keys[m * NDIM + d];
    float s = v * v;
#pragma unroll
    for (int o = 16; o; o >>= 1) s += __shfl_xor_sync(~0u, s, o);
    __shared__ float red[8];
    __shared__ float snrm;
    if ((d & 31) == 0) red[d >> 5] = s;
    __syncthreads();
    if (d == 0) {
        float t = 0.f;
        for (int ww = 0; ww < 8; ww++) t += red[ww];
        snrm = fmaxf(sqrtf(t), 1e-12f);
    }
    __syncthreads();
    out[OFF_UPMEM + (size_t)m * NDIM + d] = v / snrm;
}

extern "C" void kernel_launch(void* const* d_in, const int* in_sizes, int n_in,
                              void* d_out, int out_size) {
    const float* query = (const float*)d_in[0];
    const float* keys  = (const float*)d_in[1];
    float* out = (float*)d_out;

    cudaFuncSetAttribute(k_score,  cudaFuncAttributeMaxDynamicSharedMemorySize, 65536);
    cudaFuncSetAttribute(k_main,   cudaFuncAttributeMaxDynamicSharedMemorySize, 66048);
    cudaFuncSetAttribute(k_concat, cudaFuncAttributeMaxDynamicSharedMemorySize, 82176);

    k_score<<<256, 256, 65536>>>(query, keys);
    k_fix<<<64, 256>>>();
    k_main<<<256, 256, 66048>>>(query, keys, out);
    k_concat<<<1024, 256, 82176>>>(keys, out);
    k_mem<<<64, 256>>>(keys, out);
}